// round 16
// baseline (speedup 1.0000x reference)
#include <cuda_runtime.h>
#include <cuda_fp16.h>
#include <cuda_bf16.h>
#include <math.h>
#include <stdint.h>

#define N 2048
#define NN (N * N)

// ---------------------------------------------------------------------------
// Scratch (__device__ globals; allocation-free rule)
// ---------------------------------------------------------------------------
__device__ __nv_bfloat16 g_QKc[NN];  // cheap logits (bf16)
__device__ float  g_C1[NN];          // x @ v (fp32, row-major)
__device__ __half g_xS[2][NN];       // x      A-form
__device__ __half g_qS[2][NN];       // q^T    B-form
__device__ __half g_kS[2][NN];       // k^T    B-form
__device__ __half g_vS[2][NN];       // v^T    B-form
__device__ __half g_A1S[2][NN];      // (x@q)      A-form
__device__ __half g_B1S[2][NN];      // (x@k)^T    B-form

// ---------------------------------------------------------------------------
// PTX helpers (sm_80-era, legal on compute_103)
// ---------------------------------------------------------------------------
__device__ __forceinline__ uint32_t smem_to_u32(const void* p) {
    uint32_t a;
    asm("{ .reg .u64 t; cvta.to.shared.u64 t, %1; cvt.u32.u64 %0, t; }"
        : "=r"(a) : "l"(p));
    return a;
}
__device__ __forceinline__ void cp_async16(uint32_t saddr, const void* gaddr) {
    asm volatile("cp.async.cg.shared.global [%0], [%1], 16;"
                 :: "r"(saddr), "l"(gaddr) : "memory");
}
__device__ __forceinline__ void cp_commit() {
    asm volatile("cp.async.commit_group;" ::: "memory");
}
__device__ __forceinline__ void ldsm4(uint32_t* r, uint32_t addr) {
    asm volatile("ldmatrix.sync.aligned.m8n8.x4.shared.b16 {%0,%1,%2,%3}, [%4];"
                 : "=r"(r[0]), "=r"(r[1]), "=r"(r[2]), "=r"(r[3]) : "r"(addr));
}
__device__ __forceinline__ void mma16816(float* c, const uint32_t* a,
                                         uint32_t b0, uint32_t b1) {
    asm volatile(
        "mma.sync.aligned.m16n8k16.row.col.f32.f16.f16.f32 "
        "{%0,%1,%2,%3}, {%4,%5,%6,%7}, {%8,%9}, {%0,%1,%2,%3};"
        : "+f"(c[0]), "+f"(c[1]), "+f"(c[2]), "+f"(c[3])
        : "r"(a[0]), "r"(a[1]), "r"(a[2]), "r"(a[3]), "r"(b0), "r"(b1));
}

// ---------------------------------------------------------------------------
// Common epilogue: write 64x32 warp tile. OUT: 0=fp32, 1=fp16 planes, 2=bf16
// ---------------------------------------------------------------------------
template <int OUT>
__device__ __forceinline__ void epilogue(
    float acc[4][4][4], int brow, int bcol, int wm, int wn, int lane,
    float* Cf, __half* Cp, __nv_bfloat16* Cb)
{
    const int row0 = brow + wm * 64 + (lane >> 2);
    const int col0 = bcol + wn * 32 + (lane & 3) * 2;
#pragma unroll
    for (int mf = 0; mf < 4; mf++) {
#pragma unroll
        for (int nf = 0; nf < 4; nf++) {
#pragma unroll
            for (int hid = 0; hid < 2; hid++) {
                const size_t off = (size_t)(row0 + mf * 16 + hid * 8) * N
                                   + col0 + nf * 8;
                float c0 = acc[mf][nf][hid * 2];
                float c1 = acc[mf][nf][hid * 2 + 1];
                if (OUT == 1) {
                    __half h0 = __float2half_rn(c0);
                    __half h1 = __float2half_rn(c1);
                    __half l0 = __float2half_rn(c0 - __half2float(h0));
                    __half l1 = __float2half_rn(c1 - __half2float(h1));
                    *(__half2*)&Cp[off]              = __halves2half2(h0, h1);
                    *(__half2*)&Cp[(size_t)NN + off] = __halves2half2(l0, l1);
                } else if (OUT == 2) {
                    __nv_bfloat162 bb;
                    bb.x = __float2bfloat16_rn(c0);
                    bb.y = __float2bfloat16_rn(c1);
                    *(__nv_bfloat162*)&Cb[off] = bb;
                } else {
                    *(float2*)&Cf[off] = make_float2(c0, c1);
                }
            }
        }
    }
}

// ---------------------------------------------------------------------------
// 3-term GEMM body, BK=64, 2 stages:  C = Ah@Bh^T + Al@Bh^T + Ah@Bl^T
// Tile 128x256, 512 thr (16 warps, 2x8, 64x32 warp tile), 32 iters.
// Row stride 144B (128B data + 16B pad), conflict-free ldmatrix.
// Pipeline per iter: wait0 -> sync -> issue next loads -> compute.
// (sync at iter i guarantees compute(i-1) done in all warps, so the
//  buffer being refilled is free.)
// ---------------------------------------------------------------------------
#define TA64 18432                   // 128 rows * 144B
#define TB64 36864                   // 256 rows * 144B
#define STAGE3K64 (2 * TA64 + 2 * TB64)   // 110592 B
#define SMEM3K64 (2 * STAGE3K64)          // 221184 B

template <int OUT>
__device__ __forceinline__ void gemm3_body_k64(
    const __half* __restrict__ A, const __half* __restrict__ B,
    float* __restrict__ Cf, __half* __restrict__ Cp,
    __nv_bfloat16* __restrict__ Cb)
{
    extern __shared__ char smem[];
    const uint32_t sbase = smem_to_u32(smem);
    const int tid  = threadIdx.x;
    const int lane = tid & 31;
    const int wid  = tid >> 5;
    const int wm   = wid >> 3;
    const int wn   = wid & 7;
    const int brow = blockIdx.y * 128;
    const int bcol = blockIdx.x * 256;

    float acc[4][4][4];
#pragma unroll
    for (int i = 0; i < 4; i++)
#pragma unroll
        for (int j = 0; j < 4; j++)
#pragma unroll
            for (int q = 0; q < 4; q++) acc[i][j][q] = 0.0f;

    // loaders: per A plane 1024 chunks (2/thread); per B plane 2048 (4/thread)
    const int lrow = tid >> 3;            // 0..63
    const int lch  = tid & 7;             // 0..7

    auto load_stage = [&](int s, int k0) {
        const uint32_t st = sbase + s * STAGE3K64;
#pragma unroll
        for (int p = 0; p < 2; p++) {
            const __half* src = A + (size_t)p * NN;
#pragma unroll
            for (int rep = 0; rep < 2; rep++) {
                const int row = lrow + rep * 64;
                cp_async16(st + p * TA64 + row * 144 + lch * 16,
                           src + (size_t)(brow + row) * N + k0 + lch * 8);
            }
        }
#pragma unroll
        for (int p = 0; p < 2; p++) {
            const __half* src = B + (size_t)p * NN;
#pragma unroll
            for (int rep = 0; rep < 4; rep++) {
                const int row = lrow + rep * 64;
                cp_async16(st + 2 * TA64 + p * TB64 + row * 144 + lch * 16,
                           src + (size_t)(bcol + row) * N + k0 + lch * 8);
            }
        }
        cp_commit();
    };

    auto compute_stage = [&](int s) {
        const uint32_t st = sbase + s * STAGE3K64;
#pragma unroll
        for (int ks = 0; ks < 4; ks++) {
            uint32_t a[2][4][4];
            const uint32_t arow  = wm * 64 + (lane & 15);
            const uint32_t acol2 = (ks * 16 + ((lane >> 4) << 3)) * 2;
#pragma unroll
            for (int p = 0; p < 2; p++)
#pragma unroll
                for (int mf = 0; mf < 4; mf++)
                    ldsm4(a[p][mf],
                          st + p * TA64 + (arow + mf * 16) * 144 + acol2);

            const uint32_t brw   = wn * 32 + (lane & 7) + ((lane >> 4) << 3);
            const uint32_t bcol2 = (ks * 16 + ((lane >> 3) & 1) * 8) * 2;

            uint32_t b[2][4];
#pragma unroll
            for (int nh = 0; nh < 2; nh++)
                ldsm4(b[nh], st + 2 * TA64 + (brw + nh * 16) * 144 + bcol2);
#pragma unroll
            for (int pa = 0; pa < 2; pa++)
#pragma unroll
                for (int mf = 0; mf < 4; mf++)
#pragma unroll
                    for (int nf = 0; nf < 4; nf++)
                        mma16816(acc[mf][nf], a[pa][mf],
                                 b[nf >> 1][(nf & 1) * 2],
                                 b[nf >> 1][(nf & 1) * 2 + 1]);

#pragma unroll
            for (int nh = 0; nh < 2; nh++)
                ldsm4(b[nh],
                      st + 2 * TA64 + TB64 + (brw + nh * 16) * 144 + bcol2);
#pragma unroll
            for (int mf = 0; mf < 4; mf++)
#pragma unroll
                for (int nf = 0; nf < 4; nf++)
                    mma16816(acc[mf][nf], a[0][mf],
                             b[nf >> 1][(nf & 1) * 2],
                             b[nf >> 1][(nf & 1) * 2 + 1]);
        }
    };

    load_stage(0, 0);
    for (int it = 0; it < 32; it++) {
        asm volatile("cp.async.wait_group 0;" ::: "memory");
        __syncthreads();
        if (it + 1 < 32) load_stage((it + 1) & 1, (it + 1) * 64);
        compute_stage(it & 1);
    }

    epilogue<OUT>(acc, brow, bcol, wm, wn, lane, Cf, Cp, Cb);
}

// ---------------------------------------------------------------------------
// 1-term GEMM body, BK=128, 2 stages:  C = Ah@Bh^T
// Tile 128x256, 512 thr, 16 iters, row stride 272B (256B data + 16B pad).
// ---------------------------------------------------------------------------
#define TA128 34816                  // 128 rows * 272B
#define TB128 69632                  // 256 rows * 272B
#define STAGE1K128 (TA128 + TB128)   // 104448 B
#define SMEM1K128 (2 * STAGE1K128)   // 208896 B

template <int OUT>
__device__ __forceinline__ void gemm1_body_k128(
    const __half* __restrict__ A, const __half* __restrict__ B,
    float* __restrict__ Cf, __half* __restrict__ Cp,
    __nv_bfloat16* __restrict__ Cb)
{
    extern __shared__ char smem[];
    const uint32_t sbase = smem_to_u32(smem);
    const int tid  = threadIdx.x;
    const int lane = tid & 31;
    const int wid  = tid >> 5;
    const int wm   = wid >> 3;
    const int wn   = wid & 7;
    const int brow = blockIdx.y * 128;
    const int bcol = blockIdx.x * 256;

    float acc[4][4][4];
#pragma unroll
    for (int i = 0; i < 4; i++)
#pragma unroll
        for (int j = 0; j < 4; j++)
#pragma unroll
            for (int q = 0; q < 4; q++) acc[i][j][q] = 0.0f;

    // loaders: A = 2048 chunks (4/thread), B = 4096 chunks (8/thread)
    const int lrow = tid >> 4;            // 0..31
    const int lch  = tid & 15;            // 0..15

    auto load_stage = [&](int s, int k0) {
        const uint32_t st = sbase + s * STAGE1K128;
#pragma unroll
        for (int rep = 0; rep < 4; rep++) {
            const int row = lrow + rep * 32;
            cp_async16(st + row * 272 + lch * 16,
                       A + (size_t)(brow + row) * N + k0 + lch * 8);
        }
#pragma unroll
        for (int rep = 0; rep < 8; rep++) {
            const int row = lrow + rep * 32;
            cp_async16(st + TA128 + row * 272 + lch * 16,
                       B + (size_t)(bcol + row) * N + k0 + lch * 8);
        }
        cp_commit();
    };

    auto compute_stage = [&](int s) {
        const uint32_t st = sbase + s * STAGE1K128;
#pragma unroll
        for (int ks = 0; ks < 8; ks++) {
            uint32_t a[4][4];
            const uint32_t arow  = wm * 64 + (lane & 15);
            const uint32_t acol2 = (ks * 16 + ((lane >> 4) << 3)) * 2;
#pragma unroll
            for (int mf = 0; mf < 4; mf++)
                ldsm4(a[mf], st + (arow + mf * 16) * 272 + acol2);

            const uint32_t brw   = wn * 32 + (lane & 7) + ((lane >> 4) << 3);
            const uint32_t bcol2 = (ks * 16 + ((lane >> 3) & 1) * 8) * 2;

            uint32_t b[2][4];
#pragma unroll
            for (int nh = 0; nh < 2; nh++)
                ldsm4(b[nh], st + TA128 + (brw + nh * 16) * 272 + bcol2);
#pragma unroll
            for (int mf = 0; mf < 4; mf++)
#pragma unroll
                for (int nf = 0; nf < 4; nf++)
                    mma16816(acc[mf][nf], a[mf],
                             b[nf >> 1][(nf & 1) * 2],
                             b[nf >> 1][(nf & 1) * 2 + 1]);
        }
    };

    load_stage(0, 0);
    for (int it = 0; it < 16; it++) {
        asm volatile("cp.async.wait_group 0;" ::: "memory");
        __syncthreads();
        if (it + 1 < 16) load_stage((it + 1) & 1, (it + 1) * 128);
        compute_stage(it & 1);
    }

    epilogue<OUT>(acc, brow, bcol, wm, wn, lane, Cf, Cp, Cb);
}

// ---------------------------------------------------------------------------
// Fused layer-1: z=0 -> x@q (3-term), z=1 -> (x@k)^T (3-term),
//                z=2 -> x@v (1-term BK=128, fp32).
// ---------------------------------------------------------------------------
__global__ __launch_bounds__(512, 1) void layer1_fused_kernel(
    const __half* __restrict__ xS, const __half* __restrict__ qS,
    const __half* __restrict__ kS, const __half* __restrict__ vS,
    __half* __restrict__ A1S, __half* __restrict__ B1S,
    float* __restrict__ C1)
{
    if (blockIdx.z == 0)
        gemm3_body_k64<1>(xS, qS, nullptr, A1S, nullptr);
    else if (blockIdx.z == 1)
        gemm3_body_k64<1>(kS, xS, nullptr, B1S, nullptr);
    else
        gemm1_body_k128<0>(xS, vS, C1, nullptr, nullptr);
}

// ---------------------------------------------------------------------------
// Cheap logits: 1-term BK=128, bf16 out
// ---------------------------------------------------------------------------
__global__ __launch_bounds__(512, 1) void cheap_logits_kernel(
    const __half* __restrict__ A1S, const __half* __restrict__ B1S,
    __nv_bfloat16* __restrict__ QKc)
{
    gemm1_body_k128<2>(A1S, B1S, nullptr, nullptr, QKc);
}

// ---------------------------------------------------------------------------
// Split fp32 -> 2 fp16 planes, same layout (A-form)
// ---------------------------------------------------------------------------
__global__ __launch_bounds__(256) void split_kernel(
    const float* __restrict__ in, __half* __restrict__ out)
{
    const size_t i = (size_t)blockIdx.x * blockDim.x + threadIdx.x;
    const float2 a = *(const float2*)(in + 2 * i);
    __half hx = __float2half_rn(a.x);
    __half hy = __float2half_rn(a.y);
    __half lx = __float2half_rn(a.x - __half2float(hx));
    __half ly = __float2half_rn(a.y - __half2float(hy));
    *(__half2*)(out + 2 * i)              = __halves2half2(hx, hy);
    *(__half2*)(out + (size_t)NN + 2 * i) = __halves2half2(lx, ly);
}

// ---------------------------------------------------------------------------
// Fused split+transpose for q, k, v: fp32 [K,N] -> 2 fp16 planes [N,K].
// ---------------------------------------------------------------------------
__global__ __launch_bounds__(256) void split_transpose3_kernel(
    const float* __restrict__ q, const float* __restrict__ k,
    const float* __restrict__ v,
    __half* __restrict__ qS, __half* __restrict__ kS, __half* __restrict__ vS)
{
    __shared__ float t[64][65];
    const int tid = threadIdx.x;
    const int k0 = blockIdx.y * 64;
    const int n0 = blockIdx.x * 64;

    const float* in;
    __half* out;
    if (blockIdx.z == 0)      { in = q; out = qS; }
    else if (blockIdx.z == 1) { in = k; out = kS; }
    else                      { in = v; out = vS; }

    const int lr = tid >> 2;
    const int lc = (tid & 3) * 4;
#pragma unroll
    for (int rep = 0; rep < 4; rep++) {
        const int c = lc + rep * 16;
        const float4 f = *(const float4*)(in + (size_t)(k0 + lr) * N + n0 + c);
        t[lr][c + 0] = f.x;
        t[lr][c + 1] = f.y;
        t[lr][c + 2] = f.z;
        t[lr][c + 3] = f.w;
    }
    __syncthreads();

    const int kp = tid & 31;
    const int nb = tid >> 5;
#pragma unroll
    for (int rep = 0; rep < 8; rep++) {
        const int n = nb + rep * 8;
        const float a0 = t[2 * kp][n];
        const float a1 = t[2 * kp + 1][n];
        const __half h0 = __float2half_rn(a0);
        const __half h1 = __float2half_rn(a1);
        const __half l0 = __float2half_rn(a0 - __half2float(h0));
        const __half l1 = __float2half_rn(a1 - __half2float(h1));
        const size_t o = (size_t)(n0 + n) * N + k0 + 2 * kp;
        *(__half2*)(out + o)              = __halves2half2(h0, h1);
        *(__half2*)(out + (size_t)NN + o) = __halves2half2(l0, l1);
    }
}

// ---------------------------------------------------------------------------
// Fused candidate-refine + softmax + sparse apply. (QKc bf16)
// ---------------------------------------------------------------------------
#define MAXCAND 256

__global__ __launch_bounds__(256) void softmax_refine_apply_kernel(
    const __nv_bfloat16* __restrict__ QKc,
    const __half* __restrict__ A1S,
    const __half* __restrict__ B1S,
    const float* __restrict__ C1,
    float* __restrict__ out)
{
    __shared__ float red[256];
    __shared__ float arow[N];
    __shared__ uint32_t mask[N / 32];
    __shared__ float exlog[MAXCAND];
    __shared__ int   exidx[MAXCAND];
    __shared__ float wsh[MAXCAND + 2];

    const int row = blockIdx.x;
    const int tid = threadIdx.x;
    const __nv_bfloat16* r = QKc + (size_t)row * N;

    float vals[8];
    float lmax = -INFINITY;
#pragma unroll
    for (int i = 0; i < 8; i++) {
        vals[i] = __bfloat162float(r[tid + i * 256]);
        lmax = fmaxf(lmax, vals[i]);
    }
    red[tid] = lmax;
    if (tid < N / 32) mask[tid] = 0;
    __syncthreads();
#pragma unroll
    for (int s = 128; s > 0; s >>= 1) {
        if (tid < s) red[tid] = fmaxf(red[tid], red[tid + s]);
        __syncthreads();
    }
    const float cmax = red[0];
    __syncthreads();

    const float thresh = cmax - 12000.0f;
#pragma unroll
    for (int i = 0; i < 8; i++) {
        const int e = tid + i * 256;
        if (vals[i] >= thresh) atomicOr(&mask[e >> 5], 1u << (e & 31));
        arow[e] = __half2float(A1S[(size_t)row * N + e])
                + __half2float(A1S[(size_t)NN + (size_t)row * N + e]);
    }
    __syncthreads();

    int ncand = 0;
    for (int wrd = 0; wrd < N / 32; wrd++) {
        uint32_t mw = mask[wrd];
        while (mw && ncand < MAXCAND) {
            const int b = __ffs(mw) - 1;
            mw &= mw - 1;
            const int e = wrd * 32 + b;
            const __half* bh = B1S + (size_t)e * N;
            const __half* bl = B1S + (size_t)NN + (size_t)e * N;
            float p = 0.0f;
#pragma unroll
            for (int i = 0; i < 8; i++) {
                const int c = tid + i * 256;
                p = fmaf(arow[c],
                         __half2float(bh[c]) + __half2float(bl[c]), p);
            }
            red[tid] = p;
            __syncthreads();
#pragma unroll
            for (int s = 128; s > 0; s >>= 1) {
                if (tid < s) red[tid] += red[tid + s];
                __syncthreads();
            }
            if (tid == 0) {
                exlog[ncand] = red[0];
                exidx[ncand] = e;
            }
            __syncthreads();
            ncand++;
        }
    }

    if (tid == 0) {
        float m2 = -INFINITY;
        for (int j = 0; j < ncand; j++) m2 = fmaxf(m2, exlog[j]);
        float denom = 0.0f;
        for (int j = 0; j < ncand; j++) {
            const float w = expf(exlog[j] - m2);
            wsh[j] = w;
            denom += w;
        }
        wsh[MAXCAND] = 1.0f / denom;
    }
    __syncthreads();
    const float invd = wsh[MAXCAND];

    float acc[8];
#pragma unroll
    for (int c = 0; c < 8; c++) acc[c] = 0.0f;
    for (int j = 0; j < ncand; j++) {
        const float w = wsh[j] * invd;
        if (w != 0.0f) {
            const float* crow = C1 + (size_t)exidx[j] * N;
#pragma unroll
            for (int c = 0; c < 8; c++)
                acc[c] = fmaf(w, crow[tid + c * 256], acc[c]);
        }
    }

    float* o = out + (size_t)row * N;
#pragma unroll
    for (int c = 0; c < 8; c++) o[tid + c * 256] = acc[c];
}

// ---------------------------------------------------------------------------
// kernel_launch  —  inputs (metadata order): x, q, k, v  (float32 [N*N])
// ---------------------------------------------------------------------------
extern "C" void kernel_launch(void* const* d_in, const int* in_sizes, int n_in,
                              void* d_out, int out_size)
{
    const float* x = (const float*)d_in[0];
    const float* q = (const float*)d_in[1];
    const float* k = (const float*)d_in[2];
    const float* v = (const float*)d_in[3];
    float* out = (float*)d_out;

    __nv_bfloat16* pQKc;
    float* pC1;
    cudaGetSymbolAddress((void**)&pQKc, g_QKc);
    cudaGetSymbolAddress((void**)&pC1,  g_C1);
    __half *pxS, *pqS, *pkS, *pvS, *pA1S, *pB1S;
    cudaGetSymbolAddress((void**)&pxS,  g_xS);
    cudaGetSymbolAddress((void**)&pqS,  g_qS);
    cudaGetSymbolAddress((void**)&pkS,  g_kS);
    cudaGetSymbolAddress((void**)&pvS,  g_vS);
    cudaGetSymbolAddress((void**)&pA1S, g_A1S);
    cudaGetSymbolAddress((void**)&pB1S, g_B1S);

    cudaFuncSetAttribute(layer1_fused_kernel,
                         cudaFuncAttributeMaxDynamicSharedMemorySize, SMEM3K64);
    cudaFuncSetAttribute(cheap_logits_kernel,
                         cudaFuncAttributeMaxDynamicSharedMemorySize, SMEM1K128);

    const dim3 gGemm3(N / 256, N / 128, 3);   // heavy z=0,1 first
    const dim3 gGemm(N / 256, N / 128);
    const dim3 gSplit(NN / 512);
    const dim3 gTr3(N / 64, N / 64, 3);

    // input splits
    split_kernel<<<gSplit, 256>>>(x, pxS);
    split_transpose3_kernel<<<gTr3, 256>>>(q, k, v, pqS, pkS, pvS);

    // fused layer-1 (x@q, (x@k)^T, x@v)
    layer1_fused_kernel<<<gGemm3, 512, SMEM3K64>>>(pxS, pqS, pkS, pvS,
                                                   pA1S, pB1S, pC1);

    // cheap logits (1 term, BK=128, bf16 out)
    cheap_logits_kernel<<<gGemm, 512, SMEM1K128>>>(pA1S, pB1S, pQKc);

    // fused refine + softmax + sparse apply
    softmax_refine_apply_kernel<<<N, 256>>>(pQKc, pA1S, pB1S, pC1, out);
}